// round 12
// baseline (speedup 1.0000x reference)
#include <cuda_runtime.h>

// Mandelbrot boundary-proximity loss. R12: two-kernel pipeline.
//   phase 1 : all N, K1=8, cardioid + period-2 + period-3 filters,
//             4 pts/thread; survivors stored float4{cr,ci,zr,zi} DUAL-END
//             partitioned by |z8|^2 (>2 -> front = likely escapers,
//             else -> back = slow/in-set) so phase-2 warps are homogeneous.
//             One packed warp scan carries both bucket counts + dist sum.
//   phase 2 : iters 9..104 in one kernel (12x8 chunks, warp-vote exit every
//             8; overrun clamped exactly at 100). Fused last-block finalize.
// Continuation is lossless => identical float sequence to R9-R11
// (rel_err must remain exactly 1.769343e-06). Cycle check omitted
// (value-neutral). Exact integer ULL sum => deterministic.

#define NMAX 8388608
#define K1 8
#define P1_THREADS 256
#define P1_PTS 4
#define P2_BLOCKS 2048
#define P2_THREADS 256

__device__ unsigned long long g_sum;   // zero-init at load
__device__ unsigned int g_ns_lo;       // front bucket count
__device__ unsigned int g_ns_hi;       // back bucket count
__device__ unsigned int g_done;
__device__ float4 g_st1[NMAX];         // {cr,ci,zr,zi} after iter K1

// ---------------------------------------------------------------- phase 1
__global__ void __launch_bounds__(P1_THREADS, 7) phase1_kernel(
    const float* __restrict__ c_real,
    const float* __restrict__ c_imag,
    int n)
{
    const int tid  = blockIdx.x * P1_THREADS + threadIdx.x;
    const int base = tid * P1_PTS;
    const int lane = threadIdx.x & 31;
    const int wid  = threadIdx.x >> 5;

    float cr[P1_PTS], ci[P1_PTS];
    bool valid[P1_PTS];

    if (base + P1_PTS - 1 < n) {
        const float4 r4 = *reinterpret_cast<const float4*>(c_real + base);
        const float4 i4 = *reinterpret_cast<const float4*>(c_imag + base);
        cr[0] = r4.x; cr[1] = r4.y; cr[2] = r4.z; cr[3] = r4.w;
        ci[0] = i4.x; ci[1] = i4.y; ci[2] = i4.z; ci[3] = i4.w;
        #pragma unroll
        for (int p = 0; p < P1_PTS; ++p) valid[p] = true;
    } else {
        #pragma unroll
        for (int p = 0; p < P1_PTS; ++p) {
            valid[p] = (base + p) < n;
            cr[p] = valid[p] ? c_real[base + p] : 10.0f;  // dummy escapes fast
            ci[p] = valid[p] ? c_imag[base + p] : 0.0f;
        }
    }

    bool in_set[P1_PTS], esc[P1_PTS];
    float cnt[P1_PTS], zr[P1_PTS], zi[P1_PTS];

    #pragma unroll
    for (int p = 0; p < P1_PTS; ++p) {
        // analytic in-set: main cardioid, period-2 bulb, period-3 bulbs
        const float c2 = ci[p] * ci[p];
        const float xm = cr[p] - 0.25f;
        const float q  = xm * xm + c2;
        const float xp = cr[p] + 1.0f;
        const float ax = cr[p] + 0.1226f;
        const float ay = fabsf(ci[p]) - 0.7449f;
        in_set[p] = (q * (q + xm) < 0.25f * c2)
                  | (xp * xp + c2 < 0.0625f)
                  | (fmaf(ax, ax, ay * ay) < 0.0081f);
        esc[p] = false; cnt[p] = 0.0f; zr[p] = 0.0f; zi[p] = 0.0f;
    }

    #pragma unroll
    for (int i = 0; i < K1; ++i) {
        #pragma unroll
        for (int p = 0; p < P1_PTS; ++p) {
            float t   = fmaf(zi[p], -zi[p], cr[p]);        // cr - zi^2
            float zr2 = fmaf(zr[p],  zr[p], t);            // zr^2 + (cr - zi^2)
            float zi2 = fmaf(zr[p] + zr[p], zi[p], ci[p]);
            float mag = fmaf(zr2, zr2, zi2 * zi2);
            esc[p] |= (mag > 4.0f);          // sticky; NaN-safe post-escape
            if (!esc[p]) cnt[p] += 1.0f;
            zr[p] = zr2; zi[p] = zi2;
        }
    }

    unsigned int dist = 0;
    unsigned int maskA = 0;      // front bucket: likely soon-escapers
    unsigned int maskB = 0;      // back bucket : slow / in-set
    #pragma unroll
    for (int p = 0; p < P1_PTS; ++p) {
        if (valid[p]) {
            if (in_set[p])   dist += 70u;                  // iters = 100
            else if (esc[p]) dist += (unsigned int)(29.0f - cnt[p]);
            else {
                const float m = fmaf(zr[p], zr[p], zi[p] * zi[p]);
                if (m > 2.0f) maskA |= (1u << p);
                else          maskB |= (1u << p);
            }
        }
    }

    // ---- fused epilogue: ONE packed scan = dist sum + both bucket offsets
    // pack: [31:24] cntA, [23:16] cntB, [15:0] dist
    // (per-warp: cnt* <= 128 fits 8b; dist <= 32*4*70 = 8960 fits 16b)
    const unsigned int kA = (unsigned int)__popc(maskA);
    const unsigned int kB = (unsigned int)__popc(maskB);
    const unsigned int packed = (kA << 24) | (kB << 16) | dist;
    unsigned int incl = packed;
    #pragma unroll
    for (int off = 1; off < 32; off <<= 1) {
        unsigned int v = __shfl_up_sync(0xFFFFFFFFu, incl, off);
        if (lane >= off) incl += v;
    }
    const unsigned int excl = incl - packed;
    const unsigned int exclA = (excl >> 24) & 0xFFu;
    const unsigned int exclB = (excl >> 16) & 0xFFu;

    __shared__ unsigned int warp_pack[P1_THREADS / 32];
    __shared__ unsigned int warp_baseA[P1_THREADS / 32];
    __shared__ unsigned int warp_baseB[P1_THREADS / 32];
    __shared__ unsigned int blk_baseA, blk_baseB;
    if (lane == 31) warp_pack[wid] = incl;
    __syncthreads();

    if (threadIdx.x == 0) {
        unsigned int totA = 0, totB = 0, dist_tot = 0;
        #pragma unroll
        for (int w = 0; w < P1_THREADS / 32; ++w) {
            unsigned int pk = warp_pack[w];
            warp_baseA[w] = totA;
            warp_baseB[w] = totB;
            totA     += (pk >> 24) & 0xFFu;
            totB     += (pk >> 16) & 0xFFu;
            dist_tot +=  pk        & 0xFFFFu;
        }
        blk_baseA = totA ? atomicAdd(&g_ns_lo, totA) : 0u;
        blk_baseB = totB ? atomicAdd(&g_ns_hi, totB) : 0u;
        if (dist_tot) atomicAdd(&g_sum, (unsigned long long)dist_tot);
    }
    __syncthreads();

    if (maskA) {
        unsigned int pos = blk_baseA + warp_baseA[wid] + exclA;
        #pragma unroll
        for (int p = 0; p < P1_PTS; ++p)
            if (maskA & (1u << p)) {
                g_st1[pos] = make_float4(c_real[base + p], c_imag[base + p],
                                         zr[p], zi[p]);
                ++pos;
            }
    }
    if (maskB) {
        unsigned int pos = blk_baseB + warp_baseB[wid] + exclB;
        #pragma unroll
        for (int p = 0; p < P1_PTS; ++p)
            if (maskB & (1u << p)) {
                g_st1[(unsigned int)NMAX - 1u - pos] =
                    make_float4(c_real[base + p], c_imag[base + p],
                                zr[p], zi[p]);
                ++pos;
            }
    }
}

// ---------------------------------------------------------------- phase 2
// iters K1+1 .. K1+96 (=104; overrun clamped exactly at 100); fused finalize
__global__ void __launch_bounds__(P2_THREADS) phase2_kernel(
    float* __restrict__ out, int n)
{
    const unsigned int lo = g_ns_lo;
    const unsigned int hi = g_ns_hi;
    const unsigned int total  = lo + hi;
    const unsigned int stride = gridDim.x * blockDim.x;
    const int lane = threadIdx.x & 31;
    const int wid  = threadIdx.x >> 5;

    unsigned int local = 0;

    for (unsigned int s = blockIdx.x * blockDim.x + threadIdx.x;
         __any_sync(0xFFFFFFFFu, s < total); s += stride) {
        const bool has = (s < total);
        const unsigned int j = (s < lo) ? s
                             : (unsigned int)NMAX - 1u - (s - lo);
        const float4 st = has ? g_st1[j]
                              : make_float4(10.0f, 0.0f, 10.0f, 0.0f);
        const float cr = st.x, ci = st.y;
        float zr = st.z, zi = st.w;
        float cnt = (float)K1;
        bool esc = false;

        #pragma unroll 1
        for (int chunk = 0; chunk < 12; ++chunk) {
            #pragma unroll
            for (int jj = 0; jj < 8; ++jj) {
                float t   = fmaf(zi, -zi, cr);
                float zr2 = fmaf(zr,  zr, t);
                float zi2 = fmaf(zr + zr, zi, ci);
                float mag = fmaf(zr2, zr2, zi2 * zi2);
                esc |= (mag > 4.0f);
                if (!esc) cnt += 1.0f;
                zr = zr2; zi = zi2;
            }
            if (__all_sync(0xFFFFFFFFu, esc)) break;
        }

        if (has) {
            // escape at iter cnt+1 <= 100 -> |cnt-29|; else (cnt>99, i.e.
            // escaped past 100 or never escaped) -> 70, exactly matching
            // the reference's 100-iteration cap.
            unsigned int d = (esc && cnt <= 99.0f)
                           ? (unsigned int)fabsf(cnt - 29.0f) : 70u;
            local += d;
        }
    }

    #pragma unroll
    for (int off = 16; off > 0; off >>= 1)
        local += __shfl_down_sync(0xFFFFFFFFu, local, off);

    __shared__ unsigned int warp_sums[P2_THREADS / 32];
    if (lane == 0) warp_sums[wid] = local;
    __syncthreads();

    if (wid == 0) {
        unsigned int v = (lane < P2_THREADS / 32) ? warp_sums[lane] : 0u;
        #pragma unroll
        for (int off = 4; off > 0; off >>= 1)
            v += __shfl_down_sync(0xFFFFFFFFu, v, off);
        if (lane == 0 && v)
            atomicAdd(&g_sum, (unsigned long long)v);
    }

    // ---- last-block finalize ----
    if (threadIdx.x == 0) {
        __threadfence();
        unsigned int ticket = atomicAdd(&g_done, 1u);
        if (ticket == gridDim.x - 1u) {
            __threadfence();
            double sum = (double)g_sum;
            out[0] = (float)(sum * (0.1 / 30.0) / (double)n);
            g_sum = 0ULL;          // reset for next graph replay
            g_ns_lo = 0u;
            g_ns_hi = 0u;
            g_done = 0u;
        }
    }
}

extern "C" void kernel_launch(void* const* d_in, const int* in_sizes, int n_in,
                              void* d_out, int out_size)
{
    const float* c_real = (const float*)d_in[0];
    const float* c_imag = (const float*)d_in[1];
    float* out = (float*)d_out;
    const int n = in_sizes[0];

    const int pts_per_block = P1_THREADS * P1_PTS;
    const int p1_blocks = (n + pts_per_block - 1) / pts_per_block;
    phase1_kernel<<<p1_blocks, P1_THREADS>>>(c_real, c_imag, n);

    phase2_kernel<<<P2_BLOCKS, P2_THREADS>>>(out, n);
}

// round 13
// speedup vs baseline: 1.0040x; 1.0040x over previous
#include <cuda_runtime.h>

// Mandelbrot boundary-proximity loss. R13 = R11 pipeline (proven) + dual-end
// |z8|^2 pre-partition of phase-1 output (R12's epilogue, ~free) so phase-2a
// front-bucket warps are escape-homogeneous and vote-exit early; 2a keeps
// the STRONG iter-40 recompaction/partition for 2b (R12 showed removing it
// costs more than the merge saves).
//   phase 1 : all N, K1=8, cardioid+period-2+period-3 filters, 4 pts/thread;
//             survivors -> g_st1 dual-end by |z8|^2 (>2 front, else back).
//   phase 2a: iters 9..40 (32, chunk-4 vote); alive -> g_st2 dual-end by
//             |z40|^2.
//   phase 2b: iters 41..104 (chunk-8; overrun clamped exactly at 100);
//             fused last-block finalize.
// Lossless continuation => identical float sequences to R9-R12
// (rel_err must remain exactly 1.769343e-06). Cycle check omitted
// (value-neutral). Exact integer ULL sum => deterministic.

#define NMAX 8388608
#define K1 8
#define B2 40
#define P1_THREADS 256
#define P1_PTS 4
#define P2A_BLOCKS 2048
#define P2B_BLOCKS 768
#define P2_THREADS 256

__device__ unsigned long long g_sum;   // zero-init at load
__device__ unsigned int g_ns1_lo;      // p1 front bucket (|z8|^2 > 2)
__device__ unsigned int g_ns1_hi;      // p1 back bucket
__device__ unsigned int g_ns2_lo;      // 2a front bucket (|z40|^2 > 2)
__device__ unsigned int g_ns2_hi;      // 2a back bucket
__device__ unsigned int g_done;
__device__ float4 g_st1[NMAX];         // {cr,ci,zr,zi} after iter K1
__device__ float4 g_st2[NMAX];         // {cr,ci,zr,zi} after iter B2

// ---------------------------------------------------------------- phase 1
__global__ void __launch_bounds__(P1_THREADS, 7) phase1_kernel(
    const float* __restrict__ c_real,
    const float* __restrict__ c_imag,
    int n)
{
    const int tid  = blockIdx.x * P1_THREADS + threadIdx.x;
    const int base = tid * P1_PTS;
    const int lane = threadIdx.x & 31;
    const int wid  = threadIdx.x >> 5;

    float cr[P1_PTS], ci[P1_PTS];
    bool valid[P1_PTS];

    if (base + P1_PTS - 1 < n) {
        const float4 r4 = *reinterpret_cast<const float4*>(c_real + base);
        const float4 i4 = *reinterpret_cast<const float4*>(c_imag + base);
        cr[0] = r4.x; cr[1] = r4.y; cr[2] = r4.z; cr[3] = r4.w;
        ci[0] = i4.x; ci[1] = i4.y; ci[2] = i4.z; ci[3] = i4.w;
        #pragma unroll
        for (int p = 0; p < P1_PTS; ++p) valid[p] = true;
    } else {
        #pragma unroll
        for (int p = 0; p < P1_PTS; ++p) {
            valid[p] = (base + p) < n;
            cr[p] = valid[p] ? c_real[base + p] : 10.0f;  // dummy escapes fast
            ci[p] = valid[p] ? c_imag[base + p] : 0.0f;
        }
    }

    bool in_set[P1_PTS], esc[P1_PTS];
    float cnt[P1_PTS], zr[P1_PTS], zi[P1_PTS];

    #pragma unroll
    for (int p = 0; p < P1_PTS; ++p) {
        // analytic in-set: main cardioid, period-2 bulb, period-3 bulbs
        const float c2 = ci[p] * ci[p];
        const float xm = cr[p] - 0.25f;
        const float q  = xm * xm + c2;
        const float xp = cr[p] + 1.0f;
        const float ax = cr[p] + 0.1226f;
        const float ay = fabsf(ci[p]) - 0.7449f;
        in_set[p] = (q * (q + xm) < 0.25f * c2)
                  | (xp * xp + c2 < 0.0625f)
                  | (fmaf(ax, ax, ay * ay) < 0.0081f);
        esc[p] = false; cnt[p] = 0.0f; zr[p] = 0.0f; zi[p] = 0.0f;
    }

    #pragma unroll
    for (int i = 0; i < K1; ++i) {
        #pragma unroll
        for (int p = 0; p < P1_PTS; ++p) {
            float t   = fmaf(zi[p], -zi[p], cr[p]);        // cr - zi^2
            float zr2 = fmaf(zr[p],  zr[p], t);            // zr^2 + (cr - zi^2)
            float zi2 = fmaf(zr[p] + zr[p], zi[p], ci[p]);
            float mag = fmaf(zr2, zr2, zi2 * zi2);
            esc[p] |= (mag > 4.0f);          // sticky; NaN-safe post-escape
            if (!esc[p]) cnt[p] += 1.0f;
            zr[p] = zr2; zi[p] = zi2;
        }
    }

    unsigned int dist = 0;
    unsigned int maskA = 0;      // front: |z8|^2 > 2 (likely soon-escaper)
    unsigned int maskB = 0;      // back : slow / in-set
    #pragma unroll
    for (int p = 0; p < P1_PTS; ++p) {
        if (valid[p]) {
            if (in_set[p])   dist += 70u;                  // iters = 100
            else if (esc[p]) dist += (unsigned int)(29.0f - cnt[p]);
            else {
                const float m = fmaf(zr[p], zr[p], zi[p] * zi[p]);
                if (m > 2.0f) maskA |= (1u << p);
                else          maskB |= (1u << p);
            }
        }
    }

    // ---- fused epilogue: ONE packed scan = dist sum + both bucket offsets
    // pack: [31:24] cntA, [23:16] cntB, [15:0] dist
    // (per-warp: cnt* <= 128 fits 8b; dist <= 32*4*70 = 8960 fits 16b)
    const unsigned int kA = (unsigned int)__popc(maskA);
    const unsigned int kB = (unsigned int)__popc(maskB);
    const unsigned int packed = (kA << 24) | (kB << 16) | dist;
    unsigned int incl = packed;
    #pragma unroll
    for (int off = 1; off < 32; off <<= 1) {
        unsigned int v = __shfl_up_sync(0xFFFFFFFFu, incl, off);
        if (lane >= off) incl += v;
    }
    const unsigned int excl = incl - packed;
    const unsigned int exclA = (excl >> 24) & 0xFFu;
    const unsigned int exclB = (excl >> 16) & 0xFFu;

    __shared__ unsigned int warp_pack[P1_THREADS / 32];
    __shared__ unsigned int warp_baseA[P1_THREADS / 32];
    __shared__ unsigned int warp_baseB[P1_THREADS / 32];
    __shared__ unsigned int blk_baseA, blk_baseB;
    if (lane == 31) warp_pack[wid] = incl;
    __syncthreads();

    if (threadIdx.x == 0) {
        unsigned int totA = 0, totB = 0, dist_tot = 0;
        #pragma unroll
        for (int w = 0; w < P1_THREADS / 32; ++w) {
            unsigned int pk = warp_pack[w];
            warp_baseA[w] = totA;
            warp_baseB[w] = totB;
            totA     += (pk >> 24) & 0xFFu;
            totB     += (pk >> 16) & 0xFFu;
            dist_tot +=  pk        & 0xFFFFu;
        }
        blk_baseA = totA ? atomicAdd(&g_ns1_lo, totA) : 0u;
        blk_baseB = totB ? atomicAdd(&g_ns1_hi, totB) : 0u;
        if (dist_tot) atomicAdd(&g_sum, (unsigned long long)dist_tot);
    }
    __syncthreads();

    if (maskA) {
        unsigned int pos = blk_baseA + warp_baseA[wid] + exclA;
        #pragma unroll
        for (int p = 0; p < P1_PTS; ++p)
            if (maskA & (1u << p)) {
                g_st1[pos] = make_float4(c_real[base + p], c_imag[base + p],
                                         zr[p], zi[p]);
                ++pos;
            }
    }
    if (maskB) {
        unsigned int pos = blk_baseB + warp_baseB[wid] + exclB;
        #pragma unroll
        for (int p = 0; p < P1_PTS; ++p)
            if (maskB & (1u << p)) {
                g_st1[(unsigned int)NMAX - 1u - pos] =
                    make_float4(c_real[base + p], c_imag[base + p],
                                zr[p], zi[p]);
                ++pos;
            }
    }
}

// ---------------------------------------------------------------- phase 2a
// iters K1+1..B2 (32, chunk-4 vote) from dual-end input; strong iter-40
// partition of alive points into g_st2 (dual-end)
__global__ void __launch_bounds__(P2_THREADS) phase2a_kernel()
{
    const unsigned int lo = g_ns1_lo;
    const unsigned int hi = g_ns1_hi;
    const unsigned int total  = lo + hi;
    const unsigned int stride = gridDim.x * blockDim.x;
    const int lane = threadIdx.x & 31;
    const int wid  = threadIdx.x >> 5;

    unsigned int local = 0;

    for (unsigned int s = blockIdx.x * blockDim.x + threadIdx.x;
         __any_sync(0xFFFFFFFFu, s < total); s += stride) {
        const bool has = (s < total);
        const unsigned int j = (s < lo) ? s
                             : (unsigned int)NMAX - 1u - (s - lo);
        const float4 st = has ? g_st1[j]
                              : make_float4(10.0f, 0.0f, 10.0f, 0.0f);
        const float cr = st.x, ci = st.y;
        float zr = st.z, zi = st.w;
        float cnt = (float)K1;
        bool esc = false;

        #pragma unroll 1
        for (int chunk = 0; chunk < (B2 - K1) / 4; ++chunk) {
            #pragma unroll
            for (int jj = 0; jj < 4; ++jj) {
                float t   = fmaf(zi, -zi, cr);
                float zr2 = fmaf(zr,  zr, t);
                float zi2 = fmaf(zr + zr, zi, ci);
                float mag = fmaf(zr2, zr2, zi2 * zi2);
                esc |= (mag > 4.0f);
                if (!esc) cnt += 1.0f;
                zr = zr2; zi = zi2;
            }
            if (__all_sync(0xFFFFFFFFu, esc)) break;
        }

        if (has & esc) local += (unsigned int)fabsf(cnt - 29.0f);

        // ---- strong iter-40 dual-end re-compaction ----
        const bool surv = has & !esc;                      // cnt == B2
        const float magf = fmaf(zr, zr, zi * zi);
        const bool likely_esc = surv && (magf > 2.0f);
        const bool likely_set = surv && !(magf > 2.0f);

        const unsigned int maskA = __ballot_sync(0xFFFFFFFFu, likely_esc);
        if (maskA) {
            unsigned int b;
            if (lane == 0) b = atomicAdd(&g_ns2_lo, (unsigned int)__popc(maskA));
            b = __shfl_sync(0xFFFFFFFFu, b, 0);
            if (likely_esc) {
                unsigned int pos = b
                    + (unsigned int)__popc(maskA & ((1u << lane) - 1u));
                g_st2[pos] = make_float4(cr, ci, zr, zi);
            }
        }
        const unsigned int maskB = __ballot_sync(0xFFFFFFFFu, likely_set);
        if (maskB) {
            unsigned int b;
            if (lane == 0) b = atomicAdd(&g_ns2_hi, (unsigned int)__popc(maskB));
            b = __shfl_sync(0xFFFFFFFFu, b, 0);
            if (likely_set) {
                unsigned int pos = (unsigned int)NMAX - 1u
                    - (b + (unsigned int)__popc(maskB & ((1u << lane) - 1u)));
                g_st2[pos] = make_float4(cr, ci, zr, zi);
            }
        }
    }

    #pragma unroll
    for (int off = 16; off > 0; off >>= 1)
        local += __shfl_down_sync(0xFFFFFFFFu, local, off);

    __shared__ unsigned int warp_sums[P2_THREADS / 32];
    if (lane == 0) warp_sums[wid] = local;
    __syncthreads();

    if (wid == 0) {
        unsigned int v = (lane < P2_THREADS / 32) ? warp_sums[lane] : 0u;
        #pragma unroll
        for (int off = 4; off > 0; off >>= 1)
            v += __shfl_down_sync(0xFFFFFFFFu, v, off);
        if (lane == 0 && v)
            atomicAdd(&g_sum, (unsigned long long)v);
    }
}

// ---------------------------------------------------------------- phase 2b
// iters B2+1.. (64, overrun-clamped exactly at 100); fused finalize
__global__ void __launch_bounds__(P2_THREADS) phase2b_kernel(
    float* __restrict__ out, int n)
{
    const unsigned int lo = g_ns2_lo;
    const unsigned int hi = g_ns2_hi;
    const unsigned int total  = lo + hi;
    const unsigned int stride = gridDim.x * blockDim.x;
    const int lane = threadIdx.x & 31;
    const int wid  = threadIdx.x >> 5;

    unsigned int local = 0;

    for (unsigned int s = blockIdx.x * blockDim.x + threadIdx.x;
         __any_sync(0xFFFFFFFFu, s < total); s += stride) {
        const bool has = (s < total);
        const unsigned int j = (s < lo) ? s
                             : (unsigned int)NMAX - 1u - (s - lo);
        const float4 st = has ? g_st2[j]
                              : make_float4(10.0f, 0.0f, 10.0f, 0.0f);
        const float cr = st.x, ci = st.y;
        float zr = st.z, zi = st.w;
        float cnt = (float)B2;
        bool esc = false;

        #pragma unroll 1
        for (int chunk = 0; chunk < 8; ++chunk) {
            #pragma unroll
            for (int jj = 0; jj < 8; ++jj) {
                float t   = fmaf(zi, -zi, cr);
                float zr2 = fmaf(zr,  zr, t);
                float zi2 = fmaf(zr + zr, zi, ci);
                float mag = fmaf(zr2, zr2, zi2 * zi2);
                esc |= (mag > 4.0f);
                if (!esc) cnt += 1.0f;
                zr = zr2; zi = zi2;
            }
            if (__all_sync(0xFFFFFFFFu, esc)) break;
        }

        if (has) {
            // escape at iter cnt+1 <= 100 -> |cnt-29|; else (cnt>99) -> 70,
            // exactly matching the reference's 100-iteration cap.
            unsigned int d = (esc && cnt <= 99.0f)
                           ? (unsigned int)fabsf(cnt - 29.0f) : 70u;
            local += d;
        }
    }

    #pragma unroll
    for (int off = 16; off > 0; off >>= 1)
        local += __shfl_down_sync(0xFFFFFFFFu, local, off);

    __shared__ unsigned int warp_sums[P2_THREADS / 32];
    if (lane == 0) warp_sums[wid] = local;
    __syncthreads();

    if (wid == 0) {
        unsigned int v = (lane < P2_THREADS / 32) ? warp_sums[lane] : 0u;
        #pragma unroll
        for (int off = 4; off > 0; off >>= 1)
            v += __shfl_down_sync(0xFFFFFFFFu, v, off);
        if (lane == 0 && v)
            atomicAdd(&g_sum, (unsigned long long)v);
    }

    // ---- last-block finalize ----
    if (threadIdx.x == 0) {
        __threadfence();
        unsigned int ticket = atomicAdd(&g_done, 1u);
        if (ticket == gridDim.x - 1u) {
            __threadfence();
            double sum = (double)g_sum;
            out[0] = (float)(sum * (0.1 / 30.0) / (double)n);
            g_sum = 0ULL;          // reset for next graph replay
            g_ns1_lo = 0u;
            g_ns1_hi = 0u;
            g_ns2_lo = 0u;
            g_ns2_hi = 0u;
            g_done = 0u;
        }
    }
}

extern "C" void kernel_launch(void* const* d_in, const int* in_sizes, int n_in,
                              void* d_out, int out_size)
{
    const float* c_real = (const float*)d_in[0];
    const float* c_imag = (const float*)d_in[1];
    float* out = (float*)d_out;
    const int n = in_sizes[0];

    const int pts_per_block = P1_THREADS * P1_PTS;
    const int p1_blocks = (n + pts_per_block - 1) / pts_per_block;
    phase1_kernel<<<p1_blocks, P1_THREADS>>>(c_real, c_imag, n);

    phase2a_kernel<<<P2A_BLOCKS, P2_THREADS>>>();
    phase2b_kernel<<<P2B_BLOCKS, P2_THREADS>>>(out, n);
}

// round 14
// speedup vs baseline: 1.1039x; 1.0995x over previous
#include <cuda_runtime.h>

// Mandelbrot boundary-proximity loss. R14 = R11 (proven 60.1us) + PDL.
//   phase 1 : all N, K1=8, cardioid+period-2+period-3 filters, 4 pts/thread,
//             fused packed-scan epilogue (R11 verbatim — R13 proved epilogue
//             additions cost ~3x what they buy downstream).
//   phase 2a: iters 9..40 (chunk-4 warp-vote); alive -> g_st2 dual-end by
//             |z40|^2. Launched with programmatic stream serialization; calls
//             cudaGridDependencySynchronize() before reading p1 output.
//   phase 2b: iters 41..104 (chunk-8; overrun clamped exactly at 100), PDL,
//             fused last-block finalize.
// Lossless continuation => identical float sequences to R9-R13
// (rel_err must remain exactly 1.769343e-06). Cycle check omitted
// (value-neutral). Exact integer ULL sum => deterministic.

#define NMAX 8388608
#define K1 8
#define B2 40
#define P1_THREADS 256
#define P1_PTS 4
#define P2A_BLOCKS 2048
#define P2B_BLOCKS 768
#define P2_THREADS 256

__device__ unsigned long long g_sum;   // zero-init at load
__device__ unsigned int g_ns1;
__device__ unsigned int g_ns2_lo;      // front bucket (|z40|^2 > 2)
__device__ unsigned int g_ns2_hi;      // back bucket
__device__ unsigned int g_done;
__device__ float4 g_st1[NMAX];         // {cr,ci,zr,zi} after iter K1
__device__ float4 g_st2[NMAX];         // {cr,ci,zr,zi} after iter B2

// ---------------------------------------------------------------- phase 1
__global__ void __launch_bounds__(P1_THREADS, 7) phase1_kernel(
    const float* __restrict__ c_real,
    const float* __restrict__ c_imag,
    int n)
{
    const int tid  = blockIdx.x * P1_THREADS + threadIdx.x;
    const int base = tid * P1_PTS;
    const int lane = threadIdx.x & 31;
    const int wid  = threadIdx.x >> 5;

    float cr[P1_PTS], ci[P1_PTS];
    bool valid[P1_PTS];

    if (base + P1_PTS - 1 < n) {
        const float4 r4 = *reinterpret_cast<const float4*>(c_real + base);
        const float4 i4 = *reinterpret_cast<const float4*>(c_imag + base);
        cr[0] = r4.x; cr[1] = r4.y; cr[2] = r4.z; cr[3] = r4.w;
        ci[0] = i4.x; ci[1] = i4.y; ci[2] = i4.z; ci[3] = i4.w;
        #pragma unroll
        for (int p = 0; p < P1_PTS; ++p) valid[p] = true;
    } else {
        #pragma unroll
        for (int p = 0; p < P1_PTS; ++p) {
            valid[p] = (base + p) < n;
            cr[p] = valid[p] ? c_real[base + p] : 10.0f;  // dummy escapes fast
            ci[p] = valid[p] ? c_imag[base + p] : 0.0f;
        }
    }

    bool in_set[P1_PTS], esc[P1_PTS];
    float cnt[P1_PTS], zr[P1_PTS], zi[P1_PTS];

    #pragma unroll
    for (int p = 0; p < P1_PTS; ++p) {
        // analytic in-set: main cardioid, period-2 bulb, period-3 bulbs
        const float c2 = ci[p] * ci[p];
        const float xm = cr[p] - 0.25f;
        const float q  = xm * xm + c2;
        const float xp = cr[p] + 1.0f;
        const float ax = cr[p] + 0.1226f;
        const float ay = fabsf(ci[p]) - 0.7449f;
        in_set[p] = (q * (q + xm) < 0.25f * c2)
                  | (xp * xp + c2 < 0.0625f)
                  | (fmaf(ax, ax, ay * ay) < 0.0081f);
        esc[p] = false; cnt[p] = 0.0f; zr[p] = 0.0f; zi[p] = 0.0f;
    }

    #pragma unroll
    for (int i = 0; i < K1; ++i) {
        #pragma unroll
        for (int p = 0; p < P1_PTS; ++p) {
            float t   = fmaf(zi[p], -zi[p], cr[p]);        // cr - zi^2
            float zr2 = fmaf(zr[p],  zr[p], t);            // zr^2 + (cr - zi^2)
            float zi2 = fmaf(zr[p] + zr[p], zi[p], ci[p]);
            float mag = fmaf(zr2, zr2, zi2 * zi2);
            esc[p] |= (mag > 4.0f);          // sticky; NaN-safe post-escape
            if (!esc[p]) cnt[p] += 1.0f;
            zr[p] = zr2; zi[p] = zi2;
        }
    }

    unsigned int dist = 0;
    unsigned int smask = 0;
    #pragma unroll
    for (int p = 0; p < P1_PTS; ++p) {
        if (valid[p]) {
            if (in_set[p])   dist += 70u;                  // iters = 100
            else if (esc[p]) dist += (unsigned int)(29.0f - cnt[p]);
            else             smask |= (1u << p);
        }
    }

    // ---- fused epilogue: one packed scan = dist reduction + compaction ----
    const unsigned int k = (unsigned int)__popc(smask);
    const unsigned int packed = (k << 24) | dist;
    unsigned int incl = packed;
    #pragma unroll
    for (int off = 1; off < 32; off <<= 1) {
        unsigned int v = __shfl_up_sync(0xFFFFFFFFu, incl, off);
        if (lane >= off) incl += v;
    }
    const unsigned int excl_cnt = (incl - packed) >> 24;

    __shared__ unsigned int warp_pack[P1_THREADS / 32];
    __shared__ unsigned int warp_cbase[P1_THREADS / 32];
    __shared__ unsigned int blk_base;
    if (lane == 31) warp_pack[wid] = incl;
    __syncthreads();

    if (threadIdx.x == 0) {
        unsigned int cnt_tot = 0, dist_tot = 0;
        #pragma unroll
        for (int w = 0; w < P1_THREADS / 32; ++w) {
            unsigned int pk = warp_pack[w];
            warp_cbase[w] = cnt_tot;
            cnt_tot  += pk >> 24;
            dist_tot += pk & 0xFFFFFFu;
        }
        blk_base = cnt_tot ? atomicAdd(&g_ns1, cnt_tot) : 0u;
        if (dist_tot) atomicAdd(&g_sum, (unsigned long long)dist_tot);
    }
    __syncthreads();

    if (smask) {
        unsigned int pos = blk_base + warp_cbase[wid] + excl_cnt;
        #pragma unroll
        for (int p = 0; p < P1_PTS; ++p)
            if (smask & (1u << p)) {
                g_st1[pos] = make_float4(c_real[base + p], c_imag[base + p],
                                         zr[p], zi[p]);
                ++pos;
            }
    }
}

// ---------------------------------------------------------------- phase 2a
// iters K1+1..B2 (32, chunk-4 vote); dual-end partition alive into g_st2
__global__ void __launch_bounds__(P2_THREADS) phase2a_kernel()
{
#if __CUDA_ARCH__ >= 900
    cudaGridDependencySynchronize();   // PDL: wait for phase 1 results
#endif
    const unsigned int total  = g_ns1;
    const unsigned int stride = gridDim.x * blockDim.x;
    const int lane = threadIdx.x & 31;
    const int wid  = threadIdx.x >> 5;

    unsigned int local = 0;

    for (unsigned int s = blockIdx.x * blockDim.x + threadIdx.x;
         __any_sync(0xFFFFFFFFu, s < total); s += stride) {
        const bool has = (s < total);
        const float4 st = has ? g_st1[s]
                              : make_float4(10.0f, 0.0f, 10.0f, 0.0f);
        const float cr = st.x, ci = st.y;
        float zr = st.z, zi = st.w;
        float cnt = (float)K1;
        bool esc = false;

        #pragma unroll 1
        for (int chunk = 0; chunk < (B2 - K1) / 4; ++chunk) {
            #pragma unroll
            for (int jj = 0; jj < 4; ++jj) {
                float t   = fmaf(zi, -zi, cr);
                float zr2 = fmaf(zr,  zr, t);
                float zi2 = fmaf(zr + zr, zi, ci);
                float mag = fmaf(zr2, zr2, zi2 * zi2);
                esc |= (mag > 4.0f);
                if (!esc) cnt += 1.0f;
                zr = zr2; zi = zi2;
            }
            if (__all_sync(0xFFFFFFFFu, esc)) break;
        }

        if (has & esc) local += (unsigned int)fabsf(cnt - 29.0f);

        // ---- strong iter-40 dual-end re-compaction ----
        const bool surv = has & !esc;                      // cnt == B2
        const float magf = fmaf(zr, zr, zi * zi);
        const bool likely_esc = surv && (magf > 2.0f);

        const unsigned int smaskv = __ballot_sync(0xFFFFFFFFu, surv);
        const unsigned int maskA  = __ballot_sync(0xFFFFFFFFu, likely_esc);
        const unsigned int maskB  = smaskv & ~maskA;
        if (maskA) {
            unsigned int b;
            if (lane == 0) b = atomicAdd(&g_ns2_lo, (unsigned int)__popc(maskA));
            b = __shfl_sync(0xFFFFFFFFu, b, 0);
            if (likely_esc) {
                unsigned int pos = b
                    + (unsigned int)__popc(maskA & ((1u << lane) - 1u));
                g_st2[pos] = make_float4(cr, ci, zr, zi);
            }
        }
        if (maskB) {
            unsigned int b;
            if (lane == 0) b = atomicAdd(&g_ns2_hi, (unsigned int)__popc(maskB));
            b = __shfl_sync(0xFFFFFFFFu, b, 0);
            if (surv && !likely_esc) {
                unsigned int pos = (unsigned int)NMAX - 1u
                    - (b + (unsigned int)__popc(maskB & ((1u << lane) - 1u)));
                g_st2[pos] = make_float4(cr, ci, zr, zi);
            }
        }
    }

    #pragma unroll
    for (int off = 16; off > 0; off >>= 1)
        local += __shfl_down_sync(0xFFFFFFFFu, local, off);

    __shared__ unsigned int warp_sums[P2_THREADS / 32];
    if (lane == 0) warp_sums[wid] = local;
    __syncthreads();

    if (wid == 0) {
        unsigned int v = (lane < P2_THREADS / 32) ? warp_sums[lane] : 0u;
        #pragma unroll
        for (int off = 4; off > 0; off >>= 1)
            v += __shfl_down_sync(0xFFFFFFFFu, v, off);
        if (lane == 0 && v)
            atomicAdd(&g_sum, (unsigned long long)v);
    }
}

// ---------------------------------------------------------------- phase 2b
// iters B2+1.. (64, overrun-clamped exactly at 100); fused finalize
__global__ void __launch_bounds__(P2_THREADS) phase2b_kernel(
    float* __restrict__ out, int n)
{
#if __CUDA_ARCH__ >= 900
    cudaGridDependencySynchronize();   // PDL: wait for phase 2a results
#endif
    const unsigned int lo = g_ns2_lo;
    const unsigned int hi = g_ns2_hi;
    const unsigned int total  = lo + hi;
    const unsigned int stride = gridDim.x * blockDim.x;
    const int lane = threadIdx.x & 31;
    const int wid  = threadIdx.x >> 5;

    unsigned int local = 0;

    for (unsigned int s = blockIdx.x * blockDim.x + threadIdx.x;
         __any_sync(0xFFFFFFFFu, s < total); s += stride) {
        const bool has = (s < total);
        const unsigned int j = (s < lo) ? s
                             : (unsigned int)NMAX - 1u - (s - lo);
        const float4 st = has ? g_st2[j]
                              : make_float4(10.0f, 0.0f, 10.0f, 0.0f);
        const float cr = st.x, ci = st.y;
        float zr = st.z, zi = st.w;
        float cnt = (float)B2;
        bool esc = false;

        #pragma unroll 1
        for (int chunk = 0; chunk < 8; ++chunk) {
            #pragma unroll
            for (int jj = 0; jj < 8; ++jj) {
                float t   = fmaf(zi, -zi, cr);
                float zr2 = fmaf(zr,  zr, t);
                float zi2 = fmaf(zr + zr, zi, ci);
                float mag = fmaf(zr2, zr2, zi2 * zi2);
                esc |= (mag > 4.0f);
                if (!esc) cnt += 1.0f;
                zr = zr2; zi = zi2;
            }
            if (__all_sync(0xFFFFFFFFu, esc)) break;
        }

        if (has) {
            // escape at iter cnt+1 <= 100 -> |cnt-29|; else (cnt>99) -> 70,
            // exactly matching the reference's 100-iteration cap.
            unsigned int d = (esc && cnt <= 99.0f)
                           ? (unsigned int)fabsf(cnt - 29.0f) : 70u;
            local += d;
        }
    }

    #pragma unroll
    for (int off = 16; off > 0; off >>= 1)
        local += __shfl_down_sync(0xFFFFFFFFu, local, off);

    __shared__ unsigned int warp_sums[P2_THREADS / 32];
    if (lane == 0) warp_sums[wid] = local;
    __syncthreads();

    if (wid == 0) {
        unsigned int v = (lane < P2_THREADS / 32) ? warp_sums[lane] : 0u;
        #pragma unroll
        for (int off = 4; off > 0; off >>= 1)
            v += __shfl_down_sync(0xFFFFFFFFu, v, off);
        if (lane == 0 && v)
            atomicAdd(&g_sum, (unsigned long long)v);
    }

    // ---- last-block finalize ----
    if (threadIdx.x == 0) {
        __threadfence();
        unsigned int ticket = atomicAdd(&g_done, 1u);
        if (ticket == gridDim.x - 1u) {
            __threadfence();
            double sum = (double)g_sum;
            out[0] = (float)(sum * (0.1 / 30.0) / (double)n);
            g_sum = 0ULL;          // reset for next graph replay
            g_ns1 = 0u;
            g_ns2_lo = 0u;
            g_ns2_hi = 0u;
            g_done = 0u;
        }
    }
}

extern "C" void kernel_launch(void* const* d_in, const int* in_sizes, int n_in,
                              void* d_out, int out_size)
{
    const float* c_real = (const float*)d_in[0];
    const float* c_imag = (const float*)d_in[1];
    float* out = (float*)d_out;
    const int n = in_sizes[0];

    const int pts_per_block = P1_THREADS * P1_PTS;
    const int p1_blocks = (n + pts_per_block - 1) / pts_per_block;
    phase1_kernel<<<p1_blocks, P1_THREADS>>>(c_real, c_imag, n);

    // PDL launches: CTA setup overlaps the producer's tail; consumers gate
    // their first dependent read with cudaGridDependencySynchronize().
    cudaLaunchAttribute attr[1];
    attr[0].id = cudaLaunchAttributeProgrammaticStreamSerialization;
    attr[0].val.programmaticStreamSerializationAllowed = 1;

    cudaLaunchConfig_t cfg2a = {};
    cfg2a.gridDim  = dim3(P2A_BLOCKS);
    cfg2a.blockDim = dim3(P2_THREADS);
    cfg2a.attrs = attr;
    cfg2a.numAttrs = 1;
    cudaLaunchKernelEx(&cfg2a, phase2a_kernel);

    cudaLaunchConfig_t cfg2b = {};
    cfg2b.gridDim  = dim3(P2B_BLOCKS);
    cfg2b.blockDim = dim3(P2_THREADS);
    cfg2b.attrs = attr;
    cfg2b.numAttrs = 1;
    cudaLaunchKernelEx(&cfg2b, phase2b_kernel, out, n);
}